// round 1
// baseline (speedup 1.0000x reference)
#include <cuda_runtime.h>
#include <cuda_fp16.h>

// ---------------------------------------------------------------------------
// Problem constants
// ---------------------------------------------------------------------------
#define DMODEL 1024
#define NHEAD  16
#define HDIM   64
#define CA     384
#define TT     16
#define BB     4
#define LL     257
#define BT     (BB*TT)            // 64
#define MROWS  (BT*LL)            // 16448
#define MOFF   (BT*(LL-1))        // 16384

// ---------------------------------------------------------------------------
// Scratch (static __device__ arrays; no dynamic allocation allowed)
// ---------------------------------------------------------------------------
__device__ float g_ln  [(size_t)MROWS*DMODEL];
__device__ float g_qkv [(size_t)MROWS*3*DMODEL];
__device__ float g_attn[(size_t)MROWS*DMODEL];
__device__ float g_x1  [(size_t)MROWS*DMODEL];
__device__ float g_x2  [(size_t)MROWS*DMODEL];
__device__ float g_diff[(size_t)MOFF*DMODEL];
__device__ float g_off1[(size_t)MOFF*CA];
__device__ float g_offc[(size_t)MOFF*CA];
__device__ float g_off2[(size_t)MOFF*DMODEL];
__device__ float g_y1  [(size_t)MROWS*CA];
__device__ float g_yc  [(size_t)MROWS*CA];
__device__ float g_y2  [(size_t)MROWS*DMODEL];
__device__ float g_h   [(size_t)MROWS*4*DMODEL];

// ---------------------------------------------------------------------------
// LayerNorm: one block per row (D=1024, 256 threads x 4 elems)
// ---------------------------------------------------------------------------
__global__ __launch_bounds__(256) void ln_kernel(
    const float* __restrict__ x, const float* __restrict__ gw,
    const float* __restrict__ bw, float* __restrict__ y)
{
    __shared__ float red0[8], red1[8];
    const int row = blockIdx.x;
    const int tid = threadIdx.x;
    const float* xr = x + (size_t)row * DMODEL;
    float v[4];
    float s = 0.f, s2 = 0.f;
#pragma unroll
    for (int i = 0; i < 4; i++) {
        v[i] = xr[tid + i * 256];
        s += v[i];
        s2 += v[i] * v[i];
    }
#pragma unroll
    for (int o = 16; o > 0; o >>= 1) {
        s  += __shfl_xor_sync(0xffffffffu, s,  o);
        s2 += __shfl_xor_sync(0xffffffffu, s2, o);
    }
    if ((tid & 31) == 0) { red0[tid >> 5] = s; red1[tid >> 5] = s2; }
    __syncthreads();
    if (tid < 32) {
        float a  = (tid < 8) ? red0[tid] : 0.f;
        float a2 = (tid < 8) ? red1[tid] : 0.f;
#pragma unroll
        for (int o = 4; o > 0; o >>= 1) {
            a  += __shfl_xor_sync(0xffffffffu, a,  o);
            a2 += __shfl_xor_sync(0xffffffffu, a2, o);
        }
        if (tid == 0) { red0[0] = a; red1[0] = a2; }
    }
    __syncthreads();
    const float mean = red0[0] * (1.f / DMODEL);
    const float var  = red1[0] * (1.f / DMODEL) - mean * mean;
    const float inv  = rsqrtf(var + 1e-5f);
    float* yr = y + (size_t)row * DMODEL;
#pragma unroll
    for (int i = 0; i < 4; i++) {
        int d = tid + i * 256;
        yr[d] = (v[i] - mean) * inv * gw[d] + bw[d];
    }
}

// ---------------------------------------------------------------------------
// Generic GEMM: C[M,N] = A[M,K] @ W[N,K]^T + bias (+epilogue)
// fp32 global operands converted to fp16 in the smem stage; fp32 accumulate
// via mma.sync.m16n8k16. Tiles: BM=128, BN=128, BK=32 halves. 8 warps (2x4).
// ---------------------------------------------------------------------------
#define GBM 128
#define GBN 128
#define GBK 32
#define EPI_NONE 0
#define EPI_RES  1
#define EPI_GELU 2

template <int EPI>
__global__ __launch_bounds__(256, 2) void gemm_f16(
    const float* __restrict__ A, const float* __restrict__ W,
    const float* __restrict__ bias, const float* __restrict__ res,
    float* __restrict__ C, int M, int N, int K)
{
    __shared__ __half As[GBM][GBK + 8];
    __shared__ __half Bs[GBN][GBK + 8];

    const int tid    = threadIdx.x;
    const int lane   = tid & 31;
    const int wid    = tid >> 5;
    const int g      = lane >> 2;   // group of 4
    const int tg     = lane & 3;    // thread in group
    const int warp_m = wid & 3;     // 0..3 -> 32-row slice
    const int warp_n = wid >> 2;    // 0..1 -> 64-col slice
    const int m0 = blockIdx.y * GBM;
    const int n0 = blockIdx.x * GBN;

    float acc[2][8][4];
#pragma unroll
    for (int i = 0; i < 2; i++)
#pragma unroll
        for (int j = 0; j < 8; j++)
#pragma unroll
            for (int k = 0; k < 4; k++) acc[i][j][k] = 0.f;

    const int ktiles = K / GBK;
    for (int kt = 0; kt < ktiles; kt++) {
        // stage tiles: 128 rows x 32 halves each = 1024 float4 slots
#pragma unroll
        for (int i = 0; i < 4; i++) {
            int s   = tid + i * 256;
            int row = s >> 3;        // 8 float4 per row
            int c4  = (s & 7) * 4;
            // A tile (guard M)
            float4 fa = make_float4(0.f, 0.f, 0.f, 0.f);
            int gm = m0 + row;
            if (gm < M) fa = *(const float4*)(A + (size_t)gm * K + kt * GBK + c4);
            As[row][c4 + 0] = __float2half_rn(fa.x);
            As[row][c4 + 1] = __float2half_rn(fa.y);
            As[row][c4 + 2] = __float2half_rn(fa.z);
            As[row][c4 + 3] = __float2half_rn(fa.w);
            // B tile (N is always a multiple of 128 here)
            float4 fb = *(const float4*)(W + (size_t)(n0 + row) * K + kt * GBK + c4);
            Bs[row][c4 + 0] = __float2half_rn(fb.x);
            Bs[row][c4 + 1] = __float2half_rn(fb.y);
            Bs[row][c4 + 2] = __float2half_rn(fb.z);
            Bs[row][c4 + 3] = __float2half_rn(fb.w);
        }
        __syncthreads();

#pragma unroll
        for (int ks = 0; ks < GBK; ks += 16) {
            unsigned a[2][4];
#pragma unroll
            for (int mi = 0; mi < 2; mi++) {
                int mr = warp_m * 32 + mi * 16;
                a[mi][0] = *(const unsigned*)&As[mr + g    ][ks + tg * 2    ];
                a[mi][1] = *(const unsigned*)&As[mr + g + 8][ks + tg * 2    ];
                a[mi][2] = *(const unsigned*)&As[mr + g    ][ks + tg * 2 + 8];
                a[mi][3] = *(const unsigned*)&As[mr + g + 8][ks + tg * 2 + 8];
            }
#pragma unroll
            for (int ni = 0; ni < 8; ni++) {
                int nr = warp_n * 64 + ni * 8 + g;
                unsigned b0 = *(const unsigned*)&Bs[nr][ks + tg * 2    ];
                unsigned b1 = *(const unsigned*)&Bs[nr][ks + tg * 2 + 8];
#pragma unroll
                for (int mi = 0; mi < 2; mi++) {
                    asm volatile(
                        "mma.sync.aligned.m16n8k16.row.col.f32.f16.f16.f32 "
                        "{%0,%1,%2,%3}, {%4,%5,%6,%7}, {%8,%9}, {%0,%1,%2,%3};\n"
                        : "+f"(acc[mi][ni][0]), "+f"(acc[mi][ni][1]),
                          "+f"(acc[mi][ni][2]), "+f"(acc[mi][ni][3])
                        : "r"(a[mi][0]), "r"(a[mi][1]), "r"(a[mi][2]), "r"(a[mi][3]),
                          "r"(b0), "r"(b1));
                }
            }
        }
        __syncthreads();
    }

    // epilogue
#pragma unroll
    for (int mi = 0; mi < 2; mi++) {
#pragma unroll
        for (int ni = 0; ni < 8; ni++) {
            const int col = n0 + warp_n * 64 + ni * 8 + tg * 2;
            const float bc0 = bias[col], bc1 = bias[col + 1];
#pragma unroll
            for (int hh = 0; hh < 2; hh++) {
                int row = m0 + warp_m * 32 + mi * 16 + g + hh * 8;
                if (row < M) {
                    float v0 = acc[mi][ni][hh * 2 + 0] + bc0;
                    float v1 = acc[mi][ni][hh * 2 + 1] + bc1;
                    if (EPI == EPI_GELU) {
                        v0 = v0 / (1.f + __expf(-1.702f * v0));
                        v1 = v1 / (1.f + __expf(-1.702f * v1));
                    }
                    if (EPI == EPI_RES) {
                        v0 += res[(size_t)row * N + col];
                        v1 += res[(size_t)row * N + col + 1];
                    }
                    C[(size_t)row * N + col]     = v0;
                    C[(size_t)row * N + col + 1] = v1;
                }
            }
        }
    }
}

// ---------------------------------------------------------------------------
// Attention: one CTA per (bt, head). K,V in dynamic smem (fp32, 131.6 KB).
// One query per thread, streaming (online) softmax.
// ---------------------------------------------------------------------------
#define ATTN_SMEM (2 * LL * HDIM * (int)sizeof(float))

__global__ __launch_bounds__(288, 1) void attn_kernel(
    const float* __restrict__ qkv, float* __restrict__ out)
{
    extern __shared__ float sm[];
    float* sK = sm;
    float* sV = sm + LL * HDIM;
    const int bt = blockIdx.x >> 4;
    const int h  = blockIdx.x & 15;
    const float* base = qkv + (size_t)bt * LL * (3 * DMODEL) + h * HDIM;
    const int tid = threadIdx.x;

    for (int i = tid; i < LL * HDIM; i += 288) {
        int l = i >> 6, d = i & 63;
        const float* p = base + (size_t)l * (3 * DMODEL);
        sK[i] = p[DMODEL + d];
        sV[i] = p[2 * DMODEL + d];
    }
    __syncthreads();

    if (tid < LL) {
        float q[HDIM];
        const float* p = base + (size_t)tid * (3 * DMODEL);
#pragma unroll
        for (int d = 0; d < HDIM; d++) q[d] = p[d] * 0.125f;  // hd^-0.5

        float mx = -1e30f, ssum = 0.f;
        float acc[HDIM];
#pragma unroll
        for (int d = 0; d < HDIM; d++) acc[d] = 0.f;

        for (int k = 0; k < LL; k++) {
            const float* kv = sK + k * HDIM;
            float s = 0.f;
#pragma unroll
            for (int d = 0; d < HDIM; d++) s += q[d] * kv[d];
            if (s > mx) {
                float sc = __expf(mx - s);  // exp(-inf)=0 on first hit
                ssum *= sc;
#pragma unroll
                for (int d = 0; d < HDIM; d++) acc[d] *= sc;
                mx = s;
            }
            float pe = __expf(s - mx);
            ssum += pe;
            const float* vv = sV + k * HDIM;
#pragma unroll
            for (int d = 0; d < HDIM; d++) acc[d] += pe * vv[d];
        }
        const float inv = 1.f / ssum;
        float* o = out + ((size_t)bt * LL + tid) * DMODEL + h * HDIM;
#pragma unroll
        for (int d = 0; d < HDIM; d++) o[d] = acc[d] * inv;
    }
}

// ---------------------------------------------------------------------------
// Elementwise / conv kernels
// ---------------------------------------------------------------------------
// temporal diff of patch tokens: diff[(b,t,p),:] = x1[b,t,p+1] - x1[b,t-1,p+1]
__global__ void diff_kernel(const float* __restrict__ x1, float* __restrict__ diff)
{
    int idx = blockIdx.x * blockDim.x + threadIdx.x;
    if (idx >= MOFF * DMODEL) return;
    int d = idx & (DMODEL - 1);
    int r = idx >> 10;            // (b*T+t)*256 + p
    int p = r & 255;
    int f = r >> 8;               // b*T+t
    int t = f & (TT - 1);
    size_t cur = ((size_t)f * LL + (p + 1)) * DMODEL + d;
    float v = x1[cur];
    float prev = (t > 0) ? x1[cur - (size_t)LL * DMODEL] : v;
    diff[idx] = v - prev;
}

// depthwise 3x3 conv per frame on (64, 16, 16, CA)
__global__ void offconv_kernel(const float* __restrict__ in,
                               const float* __restrict__ cw,
                               const float* __restrict__ cb,
                               float* __restrict__ outp)
{
    int idx = blockIdx.x * blockDim.x + threadIdx.x;
    if (idx >= MOFF * CA) return;
    int c = idx % CA;
    int r = idx / CA;            // n*256 + p
    int p = r & 255;
    int n = r >> 8;
    int hh = p >> 4, ww = p & 15;
    float s = cb[c];
#pragma unroll
    for (int dh = 0; dh < 3; dh++) {
        int h2 = hh + dh - 1;
        if (h2 < 0 || h2 > 15) continue;
#pragma unroll
        for (int dw = 0; dw < 3; dw++) {
            int w2 = ww + dw - 1;
            if (w2 < 0 || w2 > 15) continue;
            s += in[((size_t)(n * 256 + h2 * 16 + w2)) * CA + c] * cw[(dh * 3 + dw) * CA + c];
        }
    }
    outp[idx] = s;
}

// depthwise conv1d along t for each (b, l, c); y1 laid out (BT, L, CA)
__global__ void aconv_kernel(const float* __restrict__ y1,
                             const float* __restrict__ aw,
                             const float* __restrict__ ab,
                             float* __restrict__ outp)
{
    int idx = blockIdx.x * blockDim.x + threadIdx.x;
    if (idx >= MROWS * CA) return;
    int c = idx % CA;
    int row = idx / CA;          // bt*L + l
    int l = row % LL;
    int bt = row / LL;
    int t = bt & (TT - 1);
    float s = ab[c];
#pragma unroll
    for (int dt = 0; dt < 3; dt++) {
        int tt = t + dt - 1;
        if (tt < 0 || tt >= TT) continue;
        s += y1[((size_t)(bt + dt - 1) * LL + l) * CA + c] * aw[dt * CA + c];
    }
    outp[idx] = s;
}

// x2 = x1 + y2 + scatter(off2) (off only on tokens l>=1)
__global__ void combine_kernel(const float* __restrict__ x1,
                               const float* __restrict__ y2,
                               const float* __restrict__ off2,
                               float* __restrict__ x2)
{
    int idx = blockIdx.x * blockDim.x + threadIdx.x;
    if (idx >= MROWS * DMODEL) return;
    int d = idx & (DMODEL - 1);
    int row = idx >> 10;         // bt*L + l
    int l = row % LL;
    int bt = row / LL;
    float v = x1[idx] + y2[idx];
    if (l > 0) v += off2[((size_t)(bt * 256 + l - 1)) * DMODEL + d];
    x2[idx] = v;
}

// ---------------------------------------------------------------------------
// Launch
// ---------------------------------------------------------------------------
extern "C" void kernel_launch(void* const* d_in, const int* in_sizes, int n_in,
                              void* d_out, int out_size)
{
    const float* x         = (const float*)d_in[0];
    const float* ln1_g     = (const float*)d_in[1];
    const float* ln1_b     = (const float*)d_in[2];
    const float* w_in      = (const float*)d_in[3];
    const float* b_in      = (const float*)d_in[4];
    const float* w_out     = (const float*)d_in[5];
    const float* b_out     = (const float*)d_in[6];
    const float* o_fc1_w   = (const float*)d_in[7];
    const float* o_fc1_b   = (const float*)d_in[8];
    const float* o_conv_w  = (const float*)d_in[9];
    const float* o_conv_b  = (const float*)d_in[10];
    const float* o_fc2_w   = (const float*)d_in[11];
    const float* o_fc2_b   = (const float*)d_in[12];
    const float* a_fc1_w   = (const float*)d_in[13];
    const float* a_fc1_b   = (const float*)d_in[14];
    const float* a_conv_w  = (const float*)d_in[15];
    const float* a_conv_b  = (const float*)d_in[16];
    const float* a_fc2_w   = (const float*)d_in[17];
    const float* a_fc2_b   = (const float*)d_in[18];
    const float* ln2_g     = (const float*)d_in[19];
    const float* ln2_b     = (const float*)d_in[20];
    const float* mlp_fc_w  = (const float*)d_in[21];
    const float* mlp_fc_b  = (const float*)d_in[22];
    const float* mlp_proj_w= (const float*)d_in[23];
    const float* mlp_proj_b= (const float*)d_in[24];
    float* outp = (float*)d_out;

    float *ln, *qkv, *attn, *x1, *x2, *diff, *off1, *offc, *off2, *y1, *yc, *y2, *h;
    cudaGetSymbolAddress((void**)&ln,   g_ln);
    cudaGetSymbolAddress((void**)&qkv,  g_qkv);
    cudaGetSymbolAddress((void**)&attn, g_attn);
    cudaGetSymbolAddress((void**)&x1,   g_x1);
    cudaGetSymbolAddress((void**)&x2,   g_x2);
    cudaGetSymbolAddress((void**)&diff, g_diff);
    cudaGetSymbolAddress((void**)&off1, g_off1);
    cudaGetSymbolAddress((void**)&offc, g_offc);
    cudaGetSymbolAddress((void**)&off2, g_off2);
    cudaGetSymbolAddress((void**)&y1,   g_y1);
    cudaGetSymbolAddress((void**)&yc,   g_yc);
    cudaGetSymbolAddress((void**)&y2,   g_y2);
    cudaGetSymbolAddress((void**)&h,    g_h);

    cudaFuncSetAttribute(attn_kernel, cudaFuncAttributeMaxDynamicSharedMemorySize, ATTN_SMEM);

    const int EW = 256;
    const int gy_full = (MROWS + GBM - 1) / GBM;  // 129
    const int gy_off  = MOFF / GBM;               // 128

    // 1) ln1
    ln_kernel<<<MROWS, 256>>>(x, ln1_g, ln1_b, ln);
    // 2) qkv = ln1 @ w_in^T + b_in
    gemm_f16<EPI_NONE><<<dim3(3 * DMODEL / GBN, gy_full), 256>>>(ln, w_in, b_in, nullptr, qkv, MROWS, 3 * DMODEL, DMODEL);
    // 3) attention
    attn_kernel<<<BT * NHEAD, 288, ATTN_SMEM>>>(qkv, attn);
    // 4) x1 = x + attn @ w_out^T + b_out
    gemm_f16<EPI_RES><<<dim3(DMODEL / GBN, gy_full), 256>>>(attn, w_out, b_out, x, x1, MROWS, DMODEL, DMODEL);
    // 5) offset path
    diff_kernel<<<(MOFF * DMODEL + EW - 1) / EW, EW>>>(x1, diff);
    gemm_f16<EPI_NONE><<<dim3(CA / GBN, gy_off), 256>>>(diff, o_fc1_w, o_fc1_b, nullptr, off1, MOFF, CA, DMODEL);
    offconv_kernel<<<(MOFF * CA + EW - 1) / EW, EW>>>(off1, o_conv_w, o_conv_b, offc);
    gemm_f16<EPI_NONE><<<dim3(DMODEL / GBN, gy_off), 256>>>(offc, o_fc2_w, o_fc2_b, nullptr, off2, MOFF, DMODEL, CA);
    // 6) adapter path
    gemm_f16<EPI_NONE><<<dim3(CA / GBN, gy_full), 256>>>(x1, a_fc1_w, a_fc1_b, nullptr, y1, MROWS, CA, DMODEL);
    aconv_kernel<<<(MROWS * CA + EW - 1) / EW, EW>>>(y1, a_conv_w, a_conv_b, yc);
    gemm_f16<EPI_NONE><<<dim3(DMODEL / GBN, gy_full), 256>>>(yc, a_fc2_w, a_fc2_b, nullptr, y2, MROWS, DMODEL, CA);
    // 7) x2 = x1 + y2 + scatter(off2)
    combine_kernel<<<(MROWS * DMODEL + EW - 1) / EW, EW>>>(x1, y2, off2, x2);
    // 8) MLP
    ln_kernel<<<MROWS, 256>>>(x2, ln2_g, ln2_b, ln);
    gemm_f16<EPI_GELU><<<dim3(4 * DMODEL / GBN, gy_full), 256>>>(ln, mlp_fc_w, mlp_fc_b, nullptr, h, MROWS, 4 * DMODEL, DMODEL);
    gemm_f16<EPI_RES><<<dim3(DMODEL / GBN, gy_full), 256>>>(h, mlp_proj_w, mlp_proj_b, x2, outp, MROWS, DMODEL, 4 * DMODEL);
}

// round 3
// speedup vs baseline: 1.8478x; 1.8478x over previous
#include <cuda_runtime.h>
#include <cuda_fp16.h>
#include <cstdint>

typedef unsigned int u32;

// ---------------------------------------------------------------------------
// Problem constants
// ---------------------------------------------------------------------------
#define DMODEL 1024
#define NHEAD  16
#define HDIM   64
#define CA     384
#define TT     16
#define BB     4
#define LL     257
#define BT     (BB*TT)            // 64
#define MROWS  (BT*LL)            // 16448
#define MOFF   (BT*(LL-1))        // 16384

// ---------------------------------------------------------------------------
// Scratch (static __device__ arrays; no dynamic allocation allowed)
// ---------------------------------------------------------------------------
// fp32
__device__ float  g_qkv [(size_t)MROWS*3*DMODEL];
__device__ float  g_x1  [(size_t)MROWS*DMODEL];
__device__ float  g_x2  [(size_t)MROWS*DMODEL];
__device__ float  g_off1[(size_t)MOFF*CA];
__device__ float  g_off2[(size_t)MOFF*DMODEL];
__device__ float  g_y1  [(size_t)MROWS*CA];
__device__ float  g_y2  [(size_t)MROWS*DMODEL];
// fp16 activations (GEMM A-side inputs)
__device__ __half h_ln  [(size_t)MROWS*DMODEL];
__device__ __half h_attn[(size_t)MROWS*DMODEL];
__device__ __half h_x1  [(size_t)MROWS*DMODEL];
__device__ __half h_diff[(size_t)MOFF*DMODEL];
__device__ __half h_offc[(size_t)MOFF*CA];
__device__ __half h_yc  [(size_t)MROWS*CA];
__device__ __half h_h   [(size_t)MROWS*4*DMODEL];
// fp16 weights
__device__ __half wh_in  [3*DMODEL*DMODEL];
__device__ __half wh_out [DMODEL*DMODEL];
__device__ __half wh_ofc1[CA*DMODEL];
__device__ __half wh_ofc2[DMODEL*CA];
__device__ __half wh_afc1[CA*DMODEL];
__device__ __half wh_afc2[DMODEL*CA];
__device__ __half wh_mfc [4*DMODEL*DMODEL];
__device__ __half wh_mpj [DMODEL*4*DMODEL];

// ---------------------------------------------------------------------------
// PTX helpers
// ---------------------------------------------------------------------------
__device__ __forceinline__ u32 smem_u32(const void* p) {
    u32 a;
    asm("{ .reg .u64 t; cvta.to.shared.u64 t, %1; cvt.u32.u64 %0, t; }"
        : "=r"(a) : "l"(p));
    return a;
}

__device__ __forceinline__ void ldmx4(u32& r0, u32& r1, u32& r2, u32& r3, u32 addr) {
    asm volatile("ldmatrix.sync.aligned.m8n8.x4.shared.b16 {%0,%1,%2,%3}, [%4];"
                 : "=r"(r0), "=r"(r1), "=r"(r2), "=r"(r3) : "r"(addr));
}

__device__ __forceinline__ void mma16816(float* c, u32 a0, u32 a1, u32 a2, u32 a3,
                                         u32 b0, u32 b1) {
    asm volatile(
        "mma.sync.aligned.m16n8k16.row.col.f32.f16.f16.f32 "
        "{%0,%1,%2,%3}, {%4,%5,%6,%7}, {%8,%9}, {%0,%1,%2,%3};\n"
        : "+f"(c[0]), "+f"(c[1]), "+f"(c[2]), "+f"(c[3])
        : "r"(a0), "r"(a1), "r"(a2), "r"(a3), "r"(b0), "r"(b1));
}

// ---------------------------------------------------------------------------
// fp32 -> fp16 conversion (weights, once per launch)
// ---------------------------------------------------------------------------
__global__ void f2h_kernel(const float* __restrict__ in, __half* __restrict__ out, int n4)
{
    int i = blockIdx.x * blockDim.x + threadIdx.x;
    if (i >= n4) return;
    float4 v = *(const float4*)(in + (size_t)i * 4);
    __half2* o = (__half2*)(out + (size_t)i * 4);
    o[0] = __floats2half2_rn(v.x, v.y);
    o[1] = __floats2half2_rn(v.z, v.w);
}

// ---------------------------------------------------------------------------
// LayerNorm: one block per row (D=1024, 256 threads x 4), fp16 output
// ---------------------------------------------------------------------------
__global__ __launch_bounds__(256) void ln_kernel(
    const float* __restrict__ x, const float* __restrict__ gw,
    const float* __restrict__ bw, __half* __restrict__ y)
{
    __shared__ float red0[8], red1[8];
    const int row = blockIdx.x;
    const int tid = threadIdx.x;
    const float* xr = x + (size_t)row * DMODEL;
    float v[4];
    float s = 0.f, s2 = 0.f;
#pragma unroll
    for (int i = 0; i < 4; i++) {
        v[i] = xr[tid + i * 256];
        s += v[i];
        s2 += v[i] * v[i];
    }
#pragma unroll
    for (int o = 16; o > 0; o >>= 1) {
        s  += __shfl_xor_sync(0xffffffffu, s,  o);
        s2 += __shfl_xor_sync(0xffffffffu, s2, o);
    }
    if ((tid & 31) == 0) { red0[tid >> 5] = s; red1[tid >> 5] = s2; }
    __syncthreads();
    if (tid < 32) {
        float a  = (tid < 8) ? red0[tid] : 0.f;
        float a2 = (tid < 8) ? red1[tid] : 0.f;
#pragma unroll
        for (int o = 4; o > 0; o >>= 1) {
            a  += __shfl_xor_sync(0xffffffffu, a,  o);
            a2 += __shfl_xor_sync(0xffffffffu, a2, o);
        }
        if (tid == 0) { red0[0] = a; red1[0] = a2; }
    }
    __syncthreads();
    const float mean = red0[0] * (1.f / DMODEL);
    const float var  = red1[0] * (1.f / DMODEL) - mean * mean;
    const float inv  = rsqrtf(var + 1e-5f);
    __half* yr = y + (size_t)row * DMODEL;
#pragma unroll
    for (int i = 0; i < 4; i++) {
        int d = tid + i * 256;
        yr[d] = __float2half_rn((v[i] - mean) * inv * gw[d] + bw[d]);
    }
}

// ---------------------------------------------------------------------------
// Pipelined fp16 GEMM: C[M,N] = A[M,K] @ W[N,K]^T + bias (+epilogue)
// 128x128x64 tiles, 3-stage cp.async, ldmatrix fragments, HMMA fp32 accum.
// EPI: 0 bias->f32 | 1 bias+res->f32 AND f16 dual | 2 bias+gelu->f16 | 3 bias+res->f32
// ---------------------------------------------------------------------------
#define GBM 128
#define GBN 128
#define GBK 64
#define STG_HALVES (128*64)                  // 8192 halves = 16KB / tile / stage
#define GEMM_SMEM  (3 * 2 * STG_HALVES * 2)  // 96KB

__device__ __forceinline__ void gemm_stage_load(
    const __half* __restrict__ A, const __half* __restrict__ W,
    int M, int K, int m0, int n0, int kt, u32 sA, u32 sB, int tid)
{
#pragma unroll
    for (int i = 0; i < 4; i++) {
        int cid = tid + i * 256;
        int row = cid >> 3, c = cid & 7;
        int sw  = ((c ^ (row & 7)) << 3);
        const __half* srcA = A + (size_t)(m0 + row) * K + kt * GBK + c * 8;
        u32 dA = sA + (u32)(row * 64 + sw) * 2;
        int szA = (m0 + row < M) ? 16 : 0;
        asm volatile("cp.async.cg.shared.global [%0], [%1], 16, %2;\n"
                     :: "r"(dA), "l"(srcA), "r"(szA));
        const __half* srcB = W + (size_t)(n0 + row) * K + kt * GBK + c * 8;
        u32 dB = sB + (u32)(row * 64 + sw) * 2;
        asm volatile("cp.async.cg.shared.global [%0], [%1], 16, 16;\n"
                     :: "r"(dB), "l"(srcB));
    }
    asm volatile("cp.async.commit_group;\n");
}

template <int EPI>
__global__ __launch_bounds__(256, 2) void gemm16(
    const __half* __restrict__ A, const __half* __restrict__ W,
    const float* __restrict__ bias, const float* __restrict__ res,
    float* __restrict__ C, __half* __restrict__ Ch,
    int M, int N, int K)
{
    extern __shared__ __half smh[];
    const u32 sbase = smem_u32(smh);

    const int tid    = threadIdx.x;
    const int lane   = tid & 31;
    const int wid    = tid >> 5;
    const int warp_m = wid & 3;
    const int warp_n = wid >> 2;
    const int m0 = blockIdx.y * GBM;
    const int n0 = blockIdx.x * GBN;
    const int mIdx = lane >> 3;     // 0..3: ldmatrix address group
    const int rIn  = lane & 7;

    float acc[2][8][4];
#pragma unroll
    for (int i = 0; i < 2; i++)
#pragma unroll
        for (int j = 0; j < 8; j++)
#pragma unroll
            for (int k = 0; k < 4; k++) acc[i][j][k] = 0.f;

    const int ktiles = K / GBK;

    // prologue: stages 0,1
    gemm_stage_load(A, W, M, K, m0, n0, 0, sbase, sbase + 3u*STG_HALVES*2, tid);
    gemm_stage_load(A, W, M, K, m0, n0, 1, sbase + 1u*STG_HALVES*2, sbase + 4u*STG_HALVES*2, tid);

    for (int kt = 0; kt < ktiles; kt++) {
        asm volatile("cp.async.wait_group 1;\n" ::: "memory");
        __syncthreads();

        if (kt + 2 < ktiles) {
            int slot = (kt + 2) % 3;
            gemm_stage_load(A, W, M, K, m0, n0, kt + 2,
                            sbase + (u32)slot * STG_HALVES * 2,
                            sbase + (u32)(3 + slot) * STG_HALVES * 2, tid);
        } else {
            asm volatile("cp.async.commit_group;\n");
        }

        const int slot = kt % 3;
        const u32 sA = sbase + (u32)slot * STG_HALVES * 2;
        const u32 sB = sbase + (u32)(3 + slot) * STG_HALVES * 2;

#pragma unroll
        for (int ks = 0; ks < 4; ks++) {
            u32 a00, a01, a02, a03, a10, a11, a12, a13;
            {
                int row   = warp_m * 32 + (mIdx & 1) * 8 + rIn;
                int chunk = ks * 2 + (mIdx >> 1);
                u32 ad0 = sA + (u32)(row * 64 + ((chunk ^ (row & 7)) << 3)) * 2;
                ldmx4(a00, a01, a02, a03, ad0);
                int row1 = row + 16;
                u32 ad1 = sA + (u32)(row1 * 64 + ((chunk ^ (row1 & 7)) << 3)) * 2;
                ldmx4(a10, a11, a12, a13, ad1);
            }
#pragma unroll
            for (int j = 0; j < 4; j++) {
                int nrow  = warp_n * 64 + j * 16 + (mIdx >> 1) * 8 + rIn;
                int chunk = ks * 2 + (mIdx & 1);
                u32 badr = sB + (u32)(nrow * 64 + ((chunk ^ (nrow & 7)) << 3)) * 2;
                u32 b0, b1, b2, b3;
                ldmx4(b0, b1, b2, b3, badr);
                mma16816(acc[0][2*j],   a00, a01, a02, a03, b0, b1);
                mma16816(acc[0][2*j+1], a00, a01, a02, a03, b2, b3);
                mma16816(acc[1][2*j],   a10, a11, a12, a13, b0, b1);
                mma16816(acc[1][2*j+1], a10, a11, a12, a13, b2, b3);
            }
        }
        __syncthreads();
    }

    // epilogue
    const int g  = lane >> 2;
    const int tg = lane & 3;
#pragma unroll
    for (int mi = 0; mi < 2; mi++) {
#pragma unroll
        for (int ni = 0; ni < 8; ni++) {
            const int col = n0 + warp_n * 64 + ni * 8 + tg * 2;
            const float bc0 = bias[col], bc1 = bias[col + 1];
#pragma unroll
            for (int hh = 0; hh < 2; hh++) {
                int row = m0 + warp_m * 32 + mi * 16 + g + hh * 8;
                if (row < M) {
                    float v0 = acc[mi][ni][hh * 2 + 0] + bc0;
                    float v1 = acc[mi][ni][hh * 2 + 1] + bc1;
                    if (EPI == 2) {
                        v0 = v0 / (1.f + __expf(-1.702f * v0));
                        v1 = v1 / (1.f + __expf(-1.702f * v1));
                        *(__half2*)(Ch + (size_t)row * N + col) = __floats2half2_rn(v0, v1);
                    } else {
                        if (EPI == 1 || EPI == 3) {
                            const float2 rr = *(const float2*)(res + (size_t)row * N + col);
                            v0 += rr.x; v1 += rr.y;
                        }
                        *(float2*)(C + (size_t)row * N + col) = make_float2(v0, v1);
                        if (EPI == 1)
                            *(__half2*)(Ch + (size_t)row * N + col) = __floats2half2_rn(v0, v1);
                    }
                }
            }
        }
    }
}

// ---------------------------------------------------------------------------
// Attention: one CTA per (bt, head). K,V in smem (fp32). One query / thread,
// streaming softmax, float4 smem access, 4-way ILP dot. fp16 output.
// ---------------------------------------------------------------------------
#define ATTN_SMEM (2 * LL * HDIM * (int)sizeof(float))

__global__ __launch_bounds__(288, 1) void attn_kernel(
    const float* __restrict__ qkv, __half* __restrict__ out)
{
    extern __shared__ float sm[];
    float4* sK4 = (float4*)sm;
    float4* sV4 = (float4*)(sm + LL * HDIM);
    const int bt = blockIdx.x >> 4;
    const int h  = blockIdx.x & 15;
    const float* base = qkv + (size_t)bt * LL * (3 * DMODEL) + h * HDIM;
    const int tid = threadIdx.x;

    const int NV4 = LL * HDIM / 4;     // 4112
    for (int i = tid; i < NV4; i += 288) {
        int l = i >> 4, d4 = i & 15;
        const float* p = base + (size_t)l * (3 * DMODEL) + d4 * 4;
        sK4[i] = *(const float4*)(p + DMODEL);
        sV4[i] = *(const float4*)(p + 2 * DMODEL);
    }
    __syncthreads();

    if (tid < LL) {
        float4 q4[16];
        const float4* p = (const float4*)(base + (size_t)tid * (3 * DMODEL));
#pragma unroll
        for (int i = 0; i < 16; i++) {
            float4 qq = p[i];
            q4[i] = make_float4(qq.x * 0.125f, qq.y * 0.125f, qq.z * 0.125f, qq.w * 0.125f);
        }

        float mx = -1e30f, ssum = 0.f;
        float acc[HDIM];
#pragma unroll
        for (int d = 0; d < HDIM; d++) acc[d] = 0.f;

        for (int k = 0; k < LL; k++) {
            const float4* kv = sK4 + k * 16;
            float s0 = 0.f, s1 = 0.f, s2 = 0.f, s3 = 0.f;
#pragma unroll
            for (int i = 0; i < 16; i++) {
                float4 kk = kv[i];
                s0 += q4[i].x * kk.x;
                s1 += q4[i].y * kk.y;
                s2 += q4[i].z * kk.z;
                s3 += q4[i].w * kk.w;
            }
            float s = (s0 + s1) + (s2 + s3);
            if (s > mx) {
                float sc = __expf(mx - s);
                ssum *= sc;
#pragma unroll
                for (int d = 0; d < HDIM; d++) acc[d] *= sc;
                mx = s;
            }
            float pe = __expf(s - mx);
            ssum += pe;
            const float4* vv = sV4 + k * 16;
#pragma unroll
            for (int i = 0; i < 16; i++) {
                float4 v = vv[i];
                acc[i*4+0] += pe * v.x;
                acc[i*4+1] += pe * v.y;
                acc[i*4+2] += pe * v.z;
                acc[i*4+3] += pe * v.w;
            }
        }
        const float inv = 1.f / ssum;
        __half2* o = (__half2*)(out + ((size_t)bt * LL + tid) * DMODEL + h * HDIM);
#pragma unroll
        for (int i = 0; i < 32; i++)
            o[i] = __floats2half2_rn(acc[2*i] * inv, acc[2*i+1] * inv);
    }
}

// ---------------------------------------------------------------------------
// Elementwise / conv kernels
// ---------------------------------------------------------------------------
__global__ void diff_kernel(const float* __restrict__ x1, __half* __restrict__ diff)
{
    int i = blockIdx.x * blockDim.x + threadIdx.x;   // handles 4 elems
    if (i >= MOFF * DMODEL / 4) return;
    int r = i >> 8;                // row: (b*T+t)*256 + p
    int p = r & 255;
    int f = r >> 8;
    int t = f & (TT - 1);
    size_t cur = ((size_t)f * LL + (p + 1)) * DMODEL + (size_t)(i & 255) * 4;
    float4 v = *(const float4*)(x1 + cur);
    float4 pv = (t > 0) ? *(const float4*)(x1 + cur - (size_t)LL * DMODEL) : v;
    __half2* o = (__half2*)(diff + (size_t)i * 4);
    o[0] = __floats2half2_rn(v.x - pv.x, v.y - pv.y);
    o[1] = __floats2half2_rn(v.z - pv.z, v.w - pv.w);
}

__global__ void offconv_kernel(const float* __restrict__ in,
                               const float* __restrict__ cw,
                               const float* __restrict__ cb,
                               __half* __restrict__ outp)
{
    int idx = blockIdx.x * blockDim.x + threadIdx.x;
    if (idx >= MOFF * CA) return;
    int c = idx % CA;
    int r = idx / CA;
    int p = r & 255;
    int n = r >> 8;
    int hh = p >> 4, ww = p & 15;
    float s = cb[c];
#pragma unroll
    for (int dh = 0; dh < 3; dh++) {
        int h2 = hh + dh - 1;
        if (h2 < 0 || h2 > 15) continue;
#pragma unroll
        for (int dw = 0; dw < 3; dw++) {
            int w2 = ww + dw - 1;
            if (w2 < 0 || w2 > 15) continue;
            s += in[((size_t)(n * 256 + h2 * 16 + w2)) * CA + c] * cw[(dh * 3 + dw) * CA + c];
        }
    }
    outp[idx] = __float2half_rn(s);
}

__global__ void aconv_kernel(const float* __restrict__ y1,
                             const float* __restrict__ aw,
                             const float* __restrict__ ab,
                             __half* __restrict__ outp)
{
    int idx = blockIdx.x * blockDim.x + threadIdx.x;
    if (idx >= MROWS * CA) return;
    int c = idx % CA;
    int row = idx / CA;
    int l = row % LL;
    int bt = row / LL;
    int t = bt & (TT - 1);
    float s = ab[c];
#pragma unroll
    for (int dt = 0; dt < 3; dt++) {
        int tt = t + dt - 1;
        if (tt < 0 || tt >= TT) continue;
        s += y1[((size_t)(bt + dt - 1) * LL + l) * CA + c] * aw[dt * CA + c];
    }
    outp[idx] = __float2half_rn(s);
}

__global__ void combine_kernel(const float* __restrict__ x1,
                               const float* __restrict__ y2,
                               const float* __restrict__ off2,
                               float* __restrict__ x2)
{
    int i = blockIdx.x * blockDim.x + threadIdx.x;   // 4 elems
    if (i >= MROWS * DMODEL / 4) return;
    int row = i >> 8;
    int l = row % LL;
    int bt = row / LL;
    float4 a = *(const float4*)(x1 + (size_t)i * 4);
    float4 b = *(const float4*)(y2 + (size_t)i * 4);
    float4 v = make_float4(a.x + b.x, a.y + b.y, a.z + b.z, a.w + b.w);
    if (l > 0) {
        const float4 c = *(const float4*)(off2 + ((size_t)(bt * 256 + l - 1) * DMODEL) + (size_t)(i & 255) * 4);
        v.x += c.x; v.y += c.y; v.z += c.z; v.w += c.w;
    }
    *(float4*)(x2 + (size_t)i * 4) = v;
}

// ---------------------------------------------------------------------------
// Launch
// ---------------------------------------------------------------------------
extern "C" void kernel_launch(void* const* d_in, const int* in_sizes, int n_in,
                              void* d_out, int out_size)
{
    const float* x         = (const float*)d_in[0];
    const float* ln1_g     = (const float*)d_in[1];
    const float* ln1_b     = (const float*)d_in[2];
    const float* w_in      = (const float*)d_in[3];
    const float* b_in      = (const float*)d_in[4];
    const float* w_out     = (const float*)d_in[5];
    const float* b_out     = (const float*)d_in[6];
    const float* o_fc1_w   = (const float*)d_in[7];
    const float* o_fc1_b   = (const float*)d_in[8];
    const float* o_conv_w  = (const float*)d_in[9];
    const float* o_conv_b  = (const float*)d_in[10];
    const float* o_fc2_w   = (const float*)d_in[11];
    const float* o_fc2_b   = (const float*)d_in[12];
    const float* a_fc1_w   = (const float*)d_in[13];
    const float* a_fc1_b   = (const float*)d_in[14];
    const float* a_conv_w  = (const float*)d_in[15];
    const float* a_conv_b  = (const float*)d_in[16];
    const float* a_fc2_w   = (const float*)d_in[17];
    const float* a_fc2_b   = (const float*)d_in[18];
    const float* ln2_g     = (const float*)d_in[19];
    const float* ln2_b     = (const float*)d_in[20];
    const float* mlp_fc_w  = (const float*)d_in[21];
    const float* mlp_fc_b  = (const float*)d_in[22];
    const float* mlp_proj_w= (const float*)d_in[23];
    const float* mlp_proj_b= (const float*)d_in[24];
    float* outp = (float*)d_out;

    float *qkv, *x1, *x2, *off1, *off2, *y1, *y2;
    __half *lnh, *attnh, *x1h, *diffh, *offch, *ych, *hhp;
    __half *win, *wout, *wofc1, *wofc2, *wafc1, *wafc2, *wmfc, *wmpj;
    cudaGetSymbolAddress((void**)&qkv,  g_qkv);
    cudaGetSymbolAddress((void**)&x1,   g_x1);
    cudaGetSymbolAddress((void**)&x2,   g_x2);
    cudaGetSymbolAddress((void**)&off1, g_off1);
    cudaGetSymbolAddress((void**)&off2, g_off2);
    cudaGetSymbolAddress((void**)&y1,   g_y1);
    cudaGetSymbolAddress((void**)&y2,   g_y2);
    cudaGetSymbolAddress((void**)&lnh,  h_ln);
    cudaGetSymbolAddress((void**)&attnh,h_attn);
    cudaGetSymbolAddress((void**)&x1h,  h_x1);
    cudaGetSymbolAddress((void**)&diffh,h_diff);
    cudaGetSymbolAddress((void**)&offch,h_offc);
    cudaGetSymbolAddress((void**)&ych,  h_yc);
    cudaGetSymbolAddress((void**)&hhp,  h_h);
    cudaGetSymbolAddress((void**)&win,  wh_in);
    cudaGetSymbolAddress((void**)&wout, wh_out);
    cudaGetSymbolAddress((void**)&wofc1,wh_ofc1);
    cudaGetSymbolAddress((void**)&wofc2,wh_ofc2);
    cudaGetSymbolAddress((void**)&wafc1,wh_afc1);
    cudaGetSymbolAddress((void**)&wafc2,wh_afc2);
    cudaGetSymbolAddress((void**)&wmfc, wh_mfc);
    cudaGetSymbolAddress((void**)&wmpj, wh_mpj);

    cudaFuncSetAttribute(attn_kernel, cudaFuncAttributeMaxDynamicSharedMemorySize, ATTN_SMEM);
    cudaFuncSetAttribute(gemm16<0>, cudaFuncAttributeMaxDynamicSharedMemorySize, GEMM_SMEM);
    cudaFuncSetAttribute(gemm16<1>, cudaFuncAttributeMaxDynamicSharedMemorySize, GEMM_SMEM);
    cudaFuncSetAttribute(gemm16<2>, cudaFuncAttributeMaxDynamicSharedMemorySize, GEMM_SMEM);
    cudaFuncSetAttribute(gemm16<3>, cudaFuncAttributeMaxDynamicSharedMemorySize, GEMM_SMEM);

    const int EW = 256;
    const int gy_full = (MROWS + GBM - 1) / GBM;  // 129
    const int gy_off  = MOFF / GBM;               // 128

    // 0) weight conversions
    f2h_kernel<<<(3*DMODEL*DMODEL/4 + 255)/256, 256>>>(w_in,       win,  3*DMODEL*DMODEL/4);
    f2h_kernel<<<(DMODEL*DMODEL/4   + 255)/256, 256>>>(w_out,      wout, DMODEL*DMODEL/4);
    f2h_kernel<<<(CA*DMODEL/4       + 255)/256, 256>>>(o_fc1_w,    wofc1, CA*DMODEL/4);
    f2h_kernel<<<(DMODEL*CA/4       + 255)/256, 256>>>(o_fc2_w,    wofc2, DMODEL*CA/4);
    f2h_kernel<<<(CA*DMODEL/4       + 255)/256, 256>>>(a_fc1_w,    wafc1, CA*DMODEL/4);
    f2h_kernel<<<(DMODEL*CA/4       + 255)/256, 256>>>(a_fc2_w,    wafc2, DMODEL*CA/4);
    f2h_kernel<<<(4*DMODEL*DMODEL/4 + 255)/256, 256>>>(mlp_fc_w,   wmfc, 4*DMODEL*DMODEL/4);
    f2h_kernel<<<(4*DMODEL*DMODEL/4 + 255)/256, 256>>>(mlp_proj_w, wmpj, 4*DMODEL*DMODEL/4);

    // 1) ln1 -> fp16
    ln_kernel<<<MROWS, 256>>>(x, ln1_g, ln1_b, lnh);
    // 2) qkv = ln1 @ w_in^T + b_in  (fp32 out)
    gemm16<0><<<dim3(3*DMODEL/GBN, gy_full), 256, GEMM_SMEM>>>(lnh, win, b_in, nullptr, qkv, nullptr, MROWS, 3*DMODEL, DMODEL);
    // 3) attention -> fp16
    attn_kernel<<<BT * NHEAD, 288, ATTN_SMEM>>>(qkv, attnh);
    // 4) x1 = x + attn @ w_out^T + b_out  (fp32 + fp16 dual)
    gemm16<1><<<dim3(DMODEL/GBN, gy_full), 256, GEMM_SMEM>>>(attnh, wout, b_out, x, x1, x1h, MROWS, DMODEL, DMODEL);
    // 5) offset path
    diff_kernel<<<(MOFF*DMODEL/4 + EW - 1)/EW, EW>>>(x1, diffh);
    gemm16<0><<<dim3(CA/GBN, gy_off), 256, GEMM_SMEM>>>(diffh, wofc1, o_fc1_b, nullptr, off1, nullptr, MOFF, CA, DMODEL);
    offconv_kernel<<<(MOFF*CA + EW - 1)/EW, EW>>>(off1, o_conv_w, o_conv_b, offch);
    gemm16<0><<<dim3(DMODEL/GBN, gy_off), 256, GEMM_SMEM>>>(offch, wofc2, o_fc2_b, nullptr, off2, nullptr, MOFF, DMODEL, CA);
    // 6) adapter path
    gemm16<0><<<dim3(CA/GBN, gy_full), 256, GEMM_SMEM>>>(x1h, wafc1, a_fc1_b, nullptr, y1, nullptr, MROWS, CA, DMODEL);
    aconv_kernel<<<(MROWS*CA + EW - 1)/EW, EW>>>(y1, a_conv_w, a_conv_b, ych);
    gemm16<0><<<dim3(DMODEL/GBN, gy_full), 256, GEMM_SMEM>>>(ych, wafc2, a_fc2_b, nullptr, y2, nullptr, MROWS, DMODEL, CA);
    // 7) x2 = x1 + y2 + scatter(off2)
    combine_kernel<<<(MROWS*DMODEL/4 + EW - 1)/EW, EW>>>(x1, y2, off2, x2);
    // 8) MLP
    ln_kernel<<<MROWS, 256>>>(x2, ln2_g, ln2_b, lnh);
    gemm16<2><<<dim3(4*DMODEL/GBN, gy_full), 256, GEMM_SMEM>>>(lnh, wmfc, mlp_fc_b, nullptr, nullptr, hhp, MROWS, 4*DMODEL, DMODEL);
    gemm16<3><<<dim3(DMODEL/GBN, gy_full), 256, GEMM_SMEM>>>(hhp, wmpj, mlp_proj_b, x2, outp, nullptr, MROWS, DMODEL, 4*DMODEL);
}